// round 16
// baseline (speedup 1.0000x reference)
#include <cuda_runtime.h>
#include <cuda_fp16.h>
#include <math.h>
#include <cstdint>

#define T_STEPS 21
#define B 4096
#define H 1024
#define E 50
#define V 96
#define G4 4096  // 4*H

#define DST 6                 // pipeline stages
#define STAGE_BYTES 8192      // A 4KB + B 4KB per k16 stage
#define SMEM_TOTAL (DST * STAGE_BYTES)

// ---------------- device globals (no allocs allowed) ----------------
// Packed fp16 row layout (1024 k): half offset = row*1024 + pack_off(k)
__device__ __align__(256) float  g_proj[V * G4];                 // [v][u*4+gate]
__device__ __align__(256) __half g_Wph[(size_t)G4 * 1024];       // W_hh: N-perm + k-pack
__device__ __align__(256) __half g_Wo[(size_t)V * 1024];         // W_out: k-pack fp16
__device__ __align__(256) __half g_h0q[(size_t)B * 1024];        // h0 fp16 packed
__device__ __align__(256) __half g_hall[(size_t)T_STEPS * B * 1024]; // all h fp16 packed
__device__ __align__(256) float  g_c[B * H];                     // cell state

__device__ __forceinline__ float tanha(float x) {
    float y;
    asm("tanh.approx.f32 %0, %1;" : "=f"(y) : "f"(x));
    return y;
}
// sigmoid via MUFU.TANH: 1 MUFU instead of 2 (EX2+RCP)
__device__ __forceinline__ float sigf(float x) {
    return fmaf(0.5f, tanha(0.5f * x), 0.5f);
}

__device__ __forceinline__ uint32_t smem_u32(const void* p) {
    uint32_t a;
    asm("{ .reg .u64 t; cvta.to.shared.u64 t, %1; cvt.u32.u64 %0, t; }" : "=r"(a) : "l"(p));
    return a;
}

// D(f32) = A(16x16 row, fp16) * B(16x8 col, fp16) + D
__device__ __forceinline__ void mma_f16_f32(float* c, uint32_t a0, uint32_t a1,
                                            uint32_t a2, uint32_t a3,
                                            uint32_t b0, uint32_t b1) {
    asm volatile(
        "mma.sync.aligned.m16n8k16.row.col.f32.f16.f16.f32 "
        "{%0,%1,%2,%3}, {%4,%5,%6,%7}, {%8,%9}, {%0,%1,%2,%3};"
        : "+f"(c[0]), "+f"(c[1]), "+f"(c[2]), "+f"(c[3])
        : "r"(a0), "r"(a1), "r"(a2), "r"(a3), "r"(b0), "r"(b1));
}

// packed half-offset of k index u within a row
__device__ __forceinline__ int pack_off(int u) {
    int kg = u >> 4, kl = u & 15, q = kl >> 1, b = kl & 1;
    int t = q & 3, ps = q >> 2;
    return kg * 16 + t * 4 + ps * 2 + b;
}

// ---------------------------------------------------------------------------
// Fused setup: one kernel, 4 independent regions selected by blockIdx.x.
//   [0, 16384)          init_state  (g_c = c0; g_h0q = pack(h0))
//   [16384, 20480)      permW       (W_hh -> g_Wph, N-perm + k-pack)
//   [20480, 21248)      vocab_proj  (g_proj)
//   [21248, 21632)      packWo      (W_out -> g_Wo)
#define SETUP_BLOCKS 21632
__global__ void setup_fused_kernel(const float* __restrict__ h0,
                                   const float* __restrict__ c0,
                                   const float* __restrict__ W_hh,
                                   const float* __restrict__ emb,
                                   const float* __restrict__ W_ih,
                                   const float* __restrict__ b_ih,
                                   const float* __restrict__ b_hh,
                                   const float* __restrict__ W_out) {
    __shared__ float es[E];
    int b = blockIdx.x;
    if (b < 16384) {
        int i = b * 256 + threadIdx.x;           // over B*H
        int m = i >> 10, u = i & 1023;
        g_c[i] = c0[i];
        g_h0q[(size_t)m * 1024 + pack_off(u)] = __float2half_rn(h0[i]);
    } else if (b < 20480) {
        int i = (b - 16384) * 256 + threadIdx.x; // over G4*256 chunks
        int n = i >> 8, c = i & 255;
        int kg = c >> 2, t = c & 3;
        int gate = (((n >> 3) & 1) << 1) | (n & 1);
        int u = ((n >> 4) << 2) | ((n >> 1) & 3);
        const float* src = W_hh + (size_t)(gate * H + u) * H + kg * 16 + 2 * t;
        float2 p0 = *reinterpret_cast<const float2*>(src);
        float2 p1 = *reinterpret_cast<const float2*>(src + 8);
        __half2 q0 = __floats2half2_rn(p0.x, p0.y);
        __half2 q1 = __floats2half2_rn(p1.x, p1.y);
        uint2 pk = make_uint2(*reinterpret_cast<uint32_t*>(&q0),
                              *reinterpret_cast<uint32_t*>(&q1));
        *reinterpret_cast<uint2*>(g_Wph + (size_t)n * 1024 + c * 4) = pk;
    } else if (b < 21248) {
        int bb = b - 20480;                      // 768 blocks: v*8 + yc
        int v = bb >> 3, yc = bb & 7;
        if (threadIdx.x < E) es[threadIdx.x] = emb[v * E + threadIdx.x];
        __syncthreads();
        int g0 = yc * 512;
        for (int g = g0 + threadIdx.x; g < g0 + 512; g += 256) {
            float s = b_ih[g] + b_hh[g];
            const float* w = W_ih + g * E;
#pragma unroll
            for (int e = 0; e < E; e++) s += es[e] * w[e];
            int gate = g >> 10;
            int u = g & (H - 1);
            g_proj[v * G4 + u * 4 + gate] = s;
        }
    } else {
        int i = (b - 21248) * 256 + threadIdx.x; // over V*H
        int v = i >> 10, k = i & 1023;
        g_Wo[(size_t)v * 1024 + pack_off(k)] = __float2half_rn(W_out[i]);
    }
}

// ---------------------------------------------------------------------------
// out_proj body for one 128-row tile at absolute row m0. Shared by the fused
// step kernel (slice t-1) and the standalone tail launch (slice T-1).
__device__ __forceinline__ void out_proj_body(int m0, const float* __restrict__ b_out,
                                              float* __restrict__ scores,
                                              uint8_t* smem, uint32_t sb) {
    const int tid = threadIdx.x;
    const int wid = tid >> 5;
    const int lane = tid & 31;
    const int gq = lane >> 2;
    const int tq = lane & 3;

    auto load_stage = [&](int s) {
        uint32_t buf = sb + (uint32_t)(s % DST) * STAGE_BYTES;
        {   // A: 256 chunks of 16B, 1/thread
            int row = tid >> 1, tt = tid & 1;
            const __half* src = g_hall + (size_t)(m0 + row) * 1024 + s * 16 + tt * 8;
            uint32_t dst = buf + (uint32_t)(row * 32 + tt * 16);
            asm volatile("cp.async.cg.shared.global [%0], [%1], 16;"
                         :: "r"(dst), "l"(src));
        }
        if (tid < 192) {  // B: 96 rows x 2 chunks
            int row = tid >> 1, tt = tid & 1;
            const __half* src = g_Wo + (size_t)row * 1024 + s * 16 + tt * 8;
            uint32_t dst = buf + 4096u + (uint32_t)(row * 32 + tt * 16);
            asm volatile("cp.async.cg.shared.global [%0], [%1], 16;"
                         :: "r"(dst), "l"(src));
        }
        asm volatile("cp.async.commit_group;" ::: "memory");
    };

    float acc[12][4];
#pragma unroll
    for (int i = 0; i < 12; i++)
#pragma unroll
        for (int j = 0; j < 4; j++) acc[i][j] = 0.f;

#pragma unroll
    for (int s = 0; s < DST - 1; s++) load_stage(s);

    for (int s = 0; s < 64; ++s) {
        asm volatile("cp.async.wait_group %0;" :: "n"(DST - 2) : "memory");
        __syncthreads();

        const uint8_t* buf = smem + (s % DST) * STAGE_BYTES;

        int rowa = 16 * wid + gq;
        uint2 A0 = *reinterpret_cast<const uint2*>(buf + rowa * 32 + tq * 8);
        uint2 A1 = *reinterpret_cast<const uint2*>(buf + (rowa + 8) * 32 + tq * 8);
#pragma unroll
        for (int ni = 0; ni < 12; ni++) {
            int row = 8 * ni + gq;
            uint2 Bf = *reinterpret_cast<const uint2*>(buf + 4096 + row * 32 + tq * 8);
            mma_f16_f32(acc[ni], A0.x, A1.x, A0.y, A1.y, Bf.x, Bf.y);
        }

        if (s + DST - 1 < 64) load_stage(s + DST - 1);
        else asm volatile("cp.async.commit_group;" ::: "memory");
    }

#pragma unroll
    for (int rsel = 0; rsel < 2; rsel++) {
        int m = m0 + 16 * wid + 8 * rsel + gq;
#pragma unroll
        for (int ni = 0; ni < 12; ni++) {
            int v = ni * 8 + tq * 2;
            float2 o;
            o.x = acc[ni][2 * rsel]     + __ldg(&b_out[v]);
            o.y = acc[ni][2 * rsel + 1] + __ldg(&b_out[v + 1]);
            *reinterpret_cast<float2*>(scores + (size_t)m * V + v) = o;
        }
    }
}

// ---------------------------------------------------------------------------
// Fused LSTM step + previous-step out_proj slice.
// grid (32, 33): y<32 -> GEMM+epilogue tile; y==32 -> proj slice for step t-1
// (h(t-1) is complete at this kernel's launch boundary).
__global__ __launch_bounds__(256, 2)
void lstm_step_fused(int t, const int* __restrict__ ids_full,
                     const float* __restrict__ b_out, float* __restrict__ out) {
    extern __shared__ __align__(128) uint8_t smem[];
    const uint32_t sb = smem_u32(smem);

    if (blockIdx.y == 32) {
        if (t == 0) return;
        out_proj_body((t - 1) * B + blockIdx.x * 128, b_out, out, smem, sb);
        return;
    }

    const int tid = threadIdx.x;
    const int wid = tid >> 5;
    const int lane = tid & 31;
    const int gq = lane >> 2;
    const int tq = lane & 3;
    const int wm = wid >> 2;       // 0..1
    const int wn = wid & 3;        // 0..3
    const int m0 = blockIdx.y * 128;
    const int n0 = blockIdx.x * 128;

    const __half* __restrict__ Asrc =
        (t == 0) ? g_h0q : (g_hall + (size_t)(t - 1) * B * 1024);
    const __half* __restrict__ Bsrc = g_Wph;

    auto load_stage = [&](int s) {
        uint32_t buf = sb + (uint32_t)(s % DST) * STAGE_BYTES;
#pragma unroll
        for (int i = 0; i < 2; i++) {
            int c = tid + (i << 8);
            int isB = c >> 8;
            int cc = c & 255;
            int row = cc >> 1, tt = cc & 1;
            const __half* src = isB
                ? (Bsrc + (size_t)(n0 + row) * 1024 + s * 16 + tt * 8)
                : (Asrc + (size_t)(m0 + row) * 1024 + s * 16 + tt * 8);
            uint32_t dst = buf + (uint32_t)(isB << 12) + (uint32_t)(row * 32 + tt * 16);
            asm volatile("cp.async.cg.shared.global [%0], [%1], 16;"
                         :: "r"(dst), "l"(src));
        }
        asm volatile("cp.async.commit_group;" ::: "memory");
    };

    float accM[4][4][4];
#pragma unroll
    for (int i = 0; i < 4; i++)
#pragma unroll
        for (int j = 0; j < 4; j++)
#pragma unroll
            for (int k = 0; k < 4; k++) accM[i][j][k] = 0.f;

#pragma unroll
    for (int s = 0; s < DST - 1; s++) load_stage(s);

    for (int s = 0; s < 64; ++s) {
        asm volatile("cp.async.wait_group %0;" :: "n"(DST - 2) : "memory");
        __syncthreads();

        const uint8_t* buf = smem + (s % DST) * STAGE_BYTES;

        uint2 Bf[4];
#pragma unroll
        for (int ni = 0; ni < 4; ni++) {
            int row = 32 * wn + 8 * ni + gq;
            Bf[ni] = *reinterpret_cast<const uint2*>(buf + 4096 + row * 32 + tq * 8);
        }
#pragma unroll
        for (int mi = 0; mi < 4; mi++) {
            int rowa = 64 * wm + 16 * mi + gq;
            uint2 A0 = *reinterpret_cast<const uint2*>(buf + rowa * 32 + tq * 8);
            uint2 A1 = *reinterpret_cast<const uint2*>(buf + (rowa + 8) * 32 + tq * 8);
#pragma unroll
            for (int ni = 0; ni < 4; ni++) {
                mma_f16_f32(accM[mi][ni], A0.x, A1.x, A0.y, A1.y, Bf[ni].x, Bf[ni].y);
            }
        }

        if (s + DST - 1 < 64) load_stage(s + DST - 1);
        else asm volatile("cp.async.commit_group;" ::: "memory");
    }

    // ---- fused LSTM epilogue ----
    const int* __restrict__ ids = ids_full + t * B;
    __half* __restrict__ hdst = g_hall + (size_t)t * B * 1024;
    const bool last = (t == T_STEPS - 1);
    float* __restrict__ out_h = out + (size_t)T_STEPS * B * V;
    float* __restrict__ out_c = out_h + (size_t)B * H;

#pragma unroll
    for (int mi = 0; mi < 4; mi++) {
#pragma unroll
        for (int rsel = 0; rsel < 2; rsel++) {
            int m = m0 + 64 * wm + 16 * mi + 8 * rsel + gq;
            int id = __ldg(&ids[m]);
            const float4* __restrict__ pv =
                reinterpret_cast<const float4*>(g_proj + (size_t)id * G4);
#pragma unroll
            for (int p = 0; p < 2; p++) {
                int u = ((n0 + 32 * wn + 16 * p) >> 2) + tq;
                float4 P = pv[u];
                int ai = 2 * rsel;
                float pre_i = accM[mi][2*p  ][ai  ] + P.x;
                float pre_f = accM[mi][2*p  ][ai+1] + P.y;
                float pre_g = accM[mi][2*p+1][ai  ] + P.z;
                float pre_o = accM[mi][2*p+1][ai+1] + P.w;
                size_t cx = (size_t)m * H + u;
                float c = sigf(pre_f) * g_c[cx] + sigf(pre_i) * tanha(pre_g);
                g_c[cx] = c;
                float h = sigf(pre_o) * tanha(c);
                hdst[(size_t)m * 1024 + pack_off(u)] = __float2half_rn(h);
                if (last) { out_h[cx] = h; out_c[cx] = c; }
            }
        }
    }
}

// ---------------------------------------------------------------------------
// standalone tail: proj slice for the last step (t = T_STEPS-1)
__global__ __launch_bounds__(256, 2)
void out_proj_tail(const float* __restrict__ b_out, float* __restrict__ scores) {
    extern __shared__ __align__(128) uint8_t smem[];
    const uint32_t sb = smem_u32(smem);
    out_proj_body((T_STEPS - 1) * B + blockIdx.x * 128, b_out, scores, smem, sb);
}

// ---------------------------------------------------------------------------
extern "C" void kernel_launch(void* const* d_in, const int* in_sizes, int n_in,
                              void* d_out, int out_size) {
    const int*   ids   = (const int*)  d_in[0];
    const float* h0    = (const float*)d_in[1];
    const float* c0    = (const float*)d_in[2];
    const float* emb   = (const float*)d_in[3];
    const float* W_ih  = (const float*)d_in[4];
    const float* W_hh  = (const float*)d_in[5];
    const float* b_ih  = (const float*)d_in[6];
    const float* b_hh  = (const float*)d_in[7];
    const float* W_out = (const float*)d_in[8];
    const float* b_out = (const float*)d_in[9];
    float* out = (float*)d_out;

    static bool inited = false;
    if (!inited) {
        inited = true;
        cudaFuncSetAttribute(lstm_step_fused, cudaFuncAttributeMaxDynamicSharedMemorySize,
                             SMEM_TOTAL);
        cudaFuncSetAttribute(out_proj_tail, cudaFuncAttributeMaxDynamicSharedMemorySize,
                             SMEM_TOTAL);
    }

    setup_fused_kernel<<<SETUP_BLOCKS, 256>>>(h0, c0, W_hh, emb, W_ih, b_ih, b_hh, W_out);

    dim3 grid(32, 33);  // 32x32 GEMM tiles + 32 proj-slice CTAs (for step t-1)
    for (int t = 0; t < T_STEPS; ++t) {
        lstm_step_fused<<<grid, 256, SMEM_TOTAL>>>(t, ids, b_out, out);
    }
    out_proj_tail<<<B / 128, 256, SMEM_TOTAL>>>(b_out, out);
}